// round 3
// baseline (speedup 1.0000x reference)
#include <cuda_runtime.h>
#include <cstdint>

// GlobalShift2dV2Portion: (16, 512, 64, 64) fp32.
// Channels [0,256): identity. Channels [256,512): per channel-group g=(c-256)>>4,
// the 16 spatial 16x16 blocks (t = a*4+e) are cyclically rotated:
//   out block t' reads input block t = (g + t') & 15.
//
// R3: permutation is closed within a 16KB (b,c) plane. One CTA per shifted
// plane: linear GMEM read -> SMEM, permute via SMEM gather, linear GMEM write.
// Both DRAM streams are now perfectly sequential. Identity half = plain copy.
// Gather-phase LDS.128 is conflict-free (adjacent ep quads have opposite e
// parity -> disjoint bank halves).

__global__ void __launch_bounds__(256) shift_perm_kernel(
    const float4* __restrict__ in, float4* __restrict__ out)
{
    __shared__ float4 sm[1024];                 // one 16KB plane
    const unsigned blk = blockIdx.x;
    const unsigned t   = threadIdx.x;

    if (blk < 4096u) {
        // Identity half: channels [0,256) of every batch.
        // j in [0, 2^22) float4 over the kept region; per batch the kept
        // region is the first 2^18 float4 of a 2^19-float4 batch slab.
        unsigned j = (blk << 10) + t;
        #pragma unroll
        for (int k = 0; k < 4; k++, j += 256u) {
            unsigned b = j >> 18;
            unsigned g = (b << 19) + (j & 0x3FFFFu);
            __stcs(out + g, __ldcs(in + g));
        }
        return;
    }

    // Shifted half: plane p -> (b = p>>8, c = 256 + (p & 255))
    const unsigned p    = blk - 4096u;
    const unsigned base = (((p >> 8) << 9) + 256u + (p & 255u)) << 10;
    const unsigned gsh  = (p & 255u) >> 4;      // channel group (rotation amount)

    // Load plane linearly (fully coalesced 128B transactions).
    #pragma unroll
    for (int k = 0; k < 4; k++)
        sm[t + 256u * k] = __ldcs(in + base + t + 256u * k);
    __syncthreads();

    // Write plane linearly, gathering the rotated block from SMEM.
    #pragma unroll
    for (int k = 0; k < 4; k++) {
        unsigned l   = t + 256u * k;            // local output float4 index
        unsigned w4  = l & 15u;
        unsigned h   = l >> 4;
        unsigned ap  = h >> 4;
        unsigned hh  = h & 15u;
        unsigned ep  = w4 >> 2;
        unsigned ww4 = w4 & 3u;
        unsigned tt  = (gsh + ap * 4u + ep) & 15u;   // source block index
        unsigned src = (((tt >> 2) * 16u + hh) << 4) + (tt & 3u) * 4u + ww4;
        __stcs(out + base + l, sm[src]);
    }
}

extern "C" void kernel_launch(void* const* d_in, const int* in_sizes, int n_in,
                              void* d_out, int out_size)
{
    const float4* in  = (const float4*)d_in[0];
    float4*       out = (float4*)d_out;
    // 4096 copy CTAs (identity half) + 4096 plane CTAs (shifted half)
    shift_perm_kernel<<<8192, 256>>>(in, out);
}

// round 4
// speedup vs baseline: 1.0993x; 1.0993x over previous
#include <cuda_runtime.h>
#include <cstdint>

// GlobalShift2dV2Portion: (16, 512, 64, 64) fp32.
// Channels [0,256): identity. Channels [256,512): per channel-group g=(c-256)>>4,
// the 16 spatial 16x16 blocks (t = a*4+e) are cyclically rotated:
//   out block t' = (t - g) mod 16 receives input block t.
//
// R4: scatter formulation. Reads are perfectly linear/coalesced (demand stream
// = memcpy-shaped); the permutation is applied on the store side (fire-and-
// forget, coalesced in L2, 64B-contiguous chunks within one 16KB plane).

static __device__ __forceinline__ unsigned dst_of(unsigned i)
{
    unsigned w4 = i & 15u;           // float4 within 64-float row
    unsigned h  = (i >> 4) & 63u;
    unsigned c  = (i >> 10) & 511u;

    if (c < 256u) return i;

    unsigned g   = (c - 256u) >> 4;  // channel group (rotation amount)
    unsigned a   = h >> 4;           // input spatial block row
    unsigned hh  = h & 15u;
    unsigned e   = w4 >> 2;          // input spatial block col
    unsigned ww4 = w4 & 3u;
    unsigned t   = a * 4u + e;       // input block index
    unsigned tp  = (t + 16u - g) & 15u;   // output block index (inverse rot)
    unsigned base = i & ~1023u;      // (b,c) plane base in float4
    return base + (((tp >> 2) * 16u + hh) << 4) + (tp & 3u) * 4u + ww4;
}

__global__ void __launch_bounds__(256) shift_scatter_kernel(
    const float4* __restrict__ in, float4* __restrict__ out)
{
    const unsigned STRIDE = 1u << 21;               // n4 / 4
    unsigned i0 = blockIdx.x * 256u + threadIdx.x;  // [0, 2^21)
    unsigned i1 = i0 + STRIDE;
    unsigned i2 = i0 + 2u * STRIDE;
    unsigned i3 = i0 + 3u * STRIDE;

    // Linear, front-batched reads (MLP=4), streaming policy.
    float4 v0 = __ldcs(in + i0);
    float4 v1 = __ldcs(in + i1);
    float4 v2 = __ldcs(in + i2);
    float4 v3 = __ldcs(in + i3);

    // Permuted stores.
    __stcs(out + dst_of(i0), v0);
    __stcs(out + dst_of(i1), v1);
    __stcs(out + dst_of(i2), v2);
    __stcs(out + dst_of(i3), v3);
}

extern "C" void kernel_launch(void* const* d_in, const int* in_sizes, int n_in,
                              void* d_out, int out_size)
{
    const float4* in  = (const float4*)d_in[0];
    float4*       out = (float4*)d_out;
    // n4 = 2^23 float4 total; 4 per thread -> 2^21 threads -> 8192 blocks of 256
    shift_scatter_kernel<<<8192, 256>>>(in, out);
}